// round 12
// baseline (speedup 1.0000x reference)
#include <cuda_runtime.h>
#include <math.h>
#include <stdint.h>

#define Bsz 32
#define Nn  128
#define Cc  128

// ---------------- scratch ----------------
constexpr size_t OFF_U  = 0;
constexpr size_t OFF_V  = OFF_U  + (size_t)Bsz*Nn*64;
constexpr size_t OFF_S  = OFF_V  + (size_t)Bsz*Nn*64;
constexpr size_t OFF_AP = OFF_S  + (size_t)Bsz*Nn*Nn;
constexpr size_t OFF_RS = OFF_AP + (size_t)Bsz*Nn*Nn;
constexpr size_t OFF_AN = OFF_RS + (size_t)Bsz*Nn;
constexpr size_t OFF_L0 = OFF_AN + (size_t)Bsz*Nn*Nn;
constexpr size_t OFF_L1 = OFF_L0 + (size_t)Bsz*Nn*Nn;
constexpr size_t OFF_M0 = OFF_L1 + (size_t)Bsz*Nn*Nn;
constexpr size_t OFF_M1 = OFF_M0 + (size_t)Bsz*Nn*Nn;
constexpr size_t OFF_ZH = OFF_M1 + (size_t)Bsz*Nn*Nn;
constexpr size_t OFF_ZL = OFF_ZH + (size_t)Bsz*Nn*1536;
constexpr size_t OFF_H0 = OFF_ZL + (size_t)Bsz*Nn*1536;
constexpr size_t OFF_H1 = OFF_H0 + (size_t)Bsz*Nn*64;
constexpr size_t OFF_H2 = OFF_H1 + (size_t)Bsz*Nn*256;
constexpr size_t TOTAL_F = OFF_H2 + (size_t)Bsz*Nn*512;

__device__ float g_buf[TOTAL_F];

// ---------------- tf32 helpers ----------------
__device__ __forceinline__ float to_tf32(float x) {
    float r;
    asm("cvt.rna.tf32.f32 %0, %1;" : "=f"(r) : "f"(x));
    return r;
}

__device__ __forceinline__ void mma_tf32(float* d,
                                         uint32_t a0, uint32_t a1, uint32_t a2, uint32_t a3,
                                         uint32_t b0, uint32_t b1) {
    asm volatile(
        "mma.sync.aligned.m16n8k8.row.col.f32.tf32.tf32.f32 "
        "{%0,%1,%2,%3}, {%4,%5,%6,%7}, {%8,%9}, {%0,%1,%2,%3};"
        : "+f"(d[0]), "+f"(d[1]), "+f"(d[2]), "+f"(d[3])
        : "r"(a0), "r"(a1), "r"(a2), "r"(a3), "r"(b0), "r"(b1));
}

// ---------------- 3xTF32 dense GEMM, A preconverted (hi/lo), fused BN epilogue ----------------
// C[M,Nc] = A@B; A given as (Ah_g, Al_g) [M,K]; B fp32 [K,Nc] converted in-kernel.
// Block tile 128x64, grid = (Nc/64, M/128). K % 16 == 0.
__global__ __launch_bounds__(256) void gemm_tc(
    const float* __restrict__ Ah_g, const float* __restrict__ Al_g, int lda,
    const float* __restrict__ B, int ldb,
    float* __restrict__ C, int ldc, int K,
    const float* __restrict__ bias,
    const float* __restrict__ rowmask,
    const float* __restrict__ bng, const float* __restrict__ bnb,
    const float* __restrict__ bnm, const float* __restrict__ bnv)
{
    __shared__ float Ah[16][136], Al[16][136];
    __shared__ float Bh[16][72],  Bl[16][72];

    const int tid  = threadIdx.x;
    const int warp = tid >> 5, lane = tid & 31;
    const int wm = warp >> 1, wn = warp & 1;
    const int g  = lane >> 2, tg = lane & 3;

    const int bm = blockIdx.y * 128, bn = blockIdx.x * 64;

    const int ar = tid >> 1;
    const int acol = (tid & 1) * 8;
    const int br = tid >> 4;
    const int bc = (tid & 15) * 4;

    float acc[2][4][4] = {};
    float4 Ah0, Ah1, Al0, Al1, Breg;

    const int nkt = K / 16;
    {
        const size_t aoff = (size_t)(bm + ar) * lda + acol;
        Ah0 = *(const float4*)(Ah_g + aoff);
        Ah1 = *(const float4*)(Ah_g + aoff + 4);
        Al0 = *(const float4*)(Al_g + aoff);
        Al1 = *(const float4*)(Al_g + aoff + 4);
        Breg = *(const float4*)(B + (size_t)br * ldb + bn + bc);
    }

    for (int t = 0; t < nkt; t++) {
        {
            const float* h0 = (const float*)&Ah0;
            const float* h1 = (const float*)&Ah1;
            const float* l0 = (const float*)&Al0;
            const float* l1 = (const float*)&Al1;
            #pragma unroll
            for (int e = 0; e < 4; e++) {
                Ah[acol + e][ar]     = h0[e];
                Ah[acol + 4 + e][ar] = h1[e];
                Al[acol + e][ar]     = l0[e];
                Al[acol + 4 + e][ar] = l1[e];
            }
            float4 h4, l4;
            const float* bv = (const float*)&Breg;
            float* hp = (float*)&h4; float* lp = (float*)&l4;
            #pragma unroll
            for (int e = 0; e < 4; e++) {
                float x = bv[e];
                float h = to_tf32(x);
                hp[e] = h; lp[e] = to_tf32(x - h);
            }
            *(float4*)&Bh[br][bc] = h4;
            *(float4*)&Bl[br][bc] = l4;
        }
        __syncthreads();

        if (t + 1 < nkt) {
            int k0 = (t + 1) * 16;
            const size_t aoff = (size_t)(bm + ar) * lda + k0 + acol;
            Ah0 = *(const float4*)(Ah_g + aoff);
            Ah1 = *(const float4*)(Ah_g + aoff + 4);
            Al0 = *(const float4*)(Al_g + aoff);
            Al1 = *(const float4*)(Al_g + aoff + 4);
            Breg = *(const float4*)(B + (size_t)(k0 + br) * ldb + bn + bc);
        }

        #pragma unroll
        for (int kb = 0; kb < 16; kb += 8) {
            uint32_t ahi[2][4], alo[2][4];
            #pragma unroll
            for (int mt = 0; mt < 2; mt++) {
                int m0 = wm * 32 + mt * 16 + g;
                ahi[mt][0] = __float_as_uint(Ah[kb + tg][m0]);
                ahi[mt][1] = __float_as_uint(Ah[kb + tg][m0 + 8]);
                ahi[mt][2] = __float_as_uint(Ah[kb + tg + 4][m0]);
                ahi[mt][3] = __float_as_uint(Ah[kb + tg + 4][m0 + 8]);
                alo[mt][0] = __float_as_uint(Al[kb + tg][m0]);
                alo[mt][1] = __float_as_uint(Al[kb + tg][m0 + 8]);
                alo[mt][2] = __float_as_uint(Al[kb + tg + 4][m0]);
                alo[mt][3] = __float_as_uint(Al[kb + tg + 4][m0 + 8]);
            }
            uint32_t bhi[4][2], blo[4][2];
            #pragma unroll
            for (int nt = 0; nt < 4; nt++) {
                int n0 = wn * 32 + nt * 8 + g;
                bhi[nt][0] = __float_as_uint(Bh[kb + tg][n0]);
                bhi[nt][1] = __float_as_uint(Bh[kb + tg + 4][n0]);
                blo[nt][0] = __float_as_uint(Bl[kb + tg][n0]);
                blo[nt][1] = __float_as_uint(Bl[kb + tg + 4][n0]);
            }
            #pragma unroll
            for (int mt = 0; mt < 2; mt++)
                #pragma unroll
                for (int nt = 0; nt < 4; nt++) {
                    mma_tf32(acc[mt][nt], ahi[mt][0], ahi[mt][1], ahi[mt][2], ahi[mt][3],
                             bhi[nt][0], bhi[nt][1]);
                    mma_tf32(acc[mt][nt], ahi[mt][0], ahi[mt][1], ahi[mt][2], ahi[mt][3],
                             blo[nt][0], blo[nt][1]);
                    mma_tf32(acc[mt][nt], alo[mt][0], alo[mt][1], alo[mt][2], alo[mt][3],
                             bhi[nt][0], bhi[nt][1]);
                }
        }
        __syncthreads();
    }

    #pragma unroll
    for (int mt = 0; mt < 2; mt++) {
        int r0 = bm + wm * 32 + mt * 16 + g;
        int r1 = r0 + 8;
        float mk0 = rowmask[r0], mk1 = rowmask[r1];
        #pragma unroll
        for (int nt = 0; nt < 4; nt++) {
            #pragma unroll
            for (int c = 0; c < 2; c++) {
                int n = bn + wn * 32 + nt * 8 + tg * 2 + c;
                float sc = bng[n] / sqrtf(bnv[n] + 1e-5f);
                float mu = bnm[n], bb = bnb[n], bi = bias[n];
                float v0 = (acc[mt][nt][c]     + bi) * mk0;
                float v1 = (acc[mt][nt][2 + c] + bi) * mk1;
                v0 = fmaxf((v0 - mu) * sc + bb, 0.0f);
                v1 = fmaxf((v1 - mu) * sc + bb, 0.0f);
                C[(size_t)r0 * ldc + n] = v0;
                C[(size_t)r1 * ldc + n] = v1;
            }
        }
    }
}

// ---------------- batched M = 2*L@L - I (3xTF32, in-kernel convert; R6-proven) ----------------
__global__ __launch_bounds__(256) void build_M(
    const float* __restrict__ L0, const float* __restrict__ L1,
    float* __restrict__ M0, float* __restrict__ M1)
{
    const int z = blockIdx.z;
    const int b = z & (Bsz - 1);
    const float* Lb = (z < Bsz ? L0 : L1) + (size_t)b * Nn * Nn;
    float* Mb = (z < Bsz ? M0 : M1) + (size_t)b * Nn * Nn;

    __shared__ float Ah[16][136], Al[16][136];
    __shared__ float Bh[16][72],  Bl[16][72];

    const int tid  = threadIdx.x;
    const int warp = tid >> 5, lane = tid & 31;
    const int wm = warp >> 1, wn = warp & 1;
    const int g  = lane >> 2, tg = lane & 3;
    const int bn = blockIdx.x * 64;

    const int ar = tid >> 1;
    const int acol = (tid & 1) * 8;
    const int br = tid >> 4;
    const int bc = (tid & 15) * 4;

    float acc[2][4][4] = {};
    float4 Areg0, Areg1, Breg;
    {
        const float* Ap = Lb + (size_t)ar * Nn + acol;
        Areg0 = *(const float4*)(Ap);
        Areg1 = *(const float4*)(Ap + 4);
        Breg  = *(const float4*)(Lb + (size_t)br * Nn + bn + bc);
    }

    for (int t = 0; t < 8; t++) {
        {
            const float* av0 = (const float*)&Areg0;
            const float* av1 = (const float*)&Areg1;
            #pragma unroll
            for (int e = 0; e < 4; e++) {
                float x = av0[e]; float h = to_tf32(x);
                Ah[acol + e][ar] = h; Al[acol + e][ar] = to_tf32(x - h);
            }
            #pragma unroll
            for (int e = 0; e < 4; e++) {
                float x = av1[e]; float h = to_tf32(x);
                Ah[acol + 4 + e][ar] = h; Al[acol + 4 + e][ar] = to_tf32(x - h);
            }
            float4 h4, l4;
            const float* bv = (const float*)&Breg;
            float* hp = (float*)&h4; float* lp = (float*)&l4;
            #pragma unroll
            for (int e = 0; e < 4; e++) {
                float x = bv[e]; float h = to_tf32(x);
                hp[e] = h; lp[e] = to_tf32(x - h);
            }
            *(float4*)&Bh[br][bc] = h4;
            *(float4*)&Bl[br][bc] = l4;
        }
        __syncthreads();

        if (t + 1 < 8) {
            int k0 = (t + 1) * 16;
            const float* Ap = Lb + (size_t)ar * Nn + k0 + acol;
            Areg0 = *(const float4*)(Ap);
            Areg1 = *(const float4*)(Ap + 4);
            Breg  = *(const float4*)(Lb + (size_t)(k0 + br) * Nn + bn + bc);
        }

        #pragma unroll
        for (int kb = 0; kb < 16; kb += 8) {
            uint32_t ahi[2][4], alo[2][4];
            #pragma unroll
            for (int mt = 0; mt < 2; mt++) {
                int m0 = wm * 32 + mt * 16 + g;
                ahi[mt][0] = __float_as_uint(Ah[kb + tg][m0]);
                ahi[mt][1] = __float_as_uint(Ah[kb + tg][m0 + 8]);
                ahi[mt][2] = __float_as_uint(Ah[kb + tg + 4][m0]);
                ahi[mt][3] = __float_as_uint(Ah[kb + tg + 4][m0 + 8]);
                alo[mt][0] = __float_as_uint(Al[kb + tg][m0]);
                alo[mt][1] = __float_as_uint(Al[kb + tg][m0 + 8]);
                alo[mt][2] = __float_as_uint(Al[kb + tg + 4][m0]);
                alo[mt][3] = __float_as_uint(Al[kb + tg + 4][m0 + 8]);
            }
            uint32_t bhi[4][2], blo[4][2];
            #pragma unroll
            for (int nt = 0; nt < 4; nt++) {
                int n0 = wn * 32 + nt * 8 + g;
                bhi[nt][0] = __float_as_uint(Bh[kb + tg][n0]);
                bhi[nt][1] = __float_as_uint(Bh[kb + tg + 4][n0]);
                blo[nt][0] = __float_as_uint(Bl[kb + tg][n0]);
                blo[nt][1] = __float_as_uint(Bl[kb + tg + 4][n0]);
            }
            #pragma unroll
            for (int mt = 0; mt < 2; mt++)
                #pragma unroll
                for (int nt = 0; nt < 4; nt++) {
                    mma_tf32(acc[mt][nt], ahi[mt][0], ahi[mt][1], ahi[mt][2], ahi[mt][3],
                             bhi[nt][0], bhi[nt][1]);
                    mma_tf32(acc[mt][nt], ahi[mt][0], ahi[mt][1], ahi[mt][2], ahi[mt][3],
                             blo[nt][0], blo[nt][1]);
                    mma_tf32(acc[mt][nt], alo[mt][0], alo[mt][1], alo[mt][2], alo[mt][3],
                             bhi[nt][0], bhi[nt][1]);
                }
        }
        __syncthreads();
    }

    #pragma unroll
    for (int mt = 0; mt < 2; mt++) {
        int r0 = wm * 32 + mt * 16 + g;
        int r1 = r0 + 8;
        #pragma unroll
        for (int nt = 0; nt < 4; nt++) {
            #pragma unroll
            for (int c = 0; c < 2; c++) {
                int n = bn + wn * 32 + nt * 8 + tg * 2 + c;
                float v0 = 2.0f * acc[mt][nt][c]     - (r0 == n ? 1.0f : 0.0f);
                float v1 = 2.0f * acc[mt][nt][2 + c] - (r1 == n ? 1.0f : 0.0f);
                Mb[(size_t)r0 * Nn + n] = v0;
                Mb[(size_t)r1 * Nn + n] = v1;
            }
        }
    }
}

// ---------------- batched Chebyshev products into hi/lo Z slices (3xTF32) ----------------
// grid: (fin/64, 1, 4*Bsz). sel = z>>5: 0->L0 s1, 1->M0 s2, 2->L1 s4, 3->M1 s5.
__global__ __launch_bounds__(256) void cheb_tc(
    const float* __restrict__ L0, const float* __restrict__ M0,
    const float* __restrict__ L1, const float* __restrict__ M1,
    const float* __restrict__ X, int ldx,
    float* __restrict__ Zh, float* __restrict__ Zl, int ldz, int fin)
{
    const int z = blockIdx.z;
    const int b = z & (Bsz - 1);
    const int sel = z >> 5;
    const float* G = (sel == 0 ? L0 : sel == 1 ? M0 : sel == 2 ? L1 : M1)
                     + (size_t)b * Nn * Nn;
    const int slice = (sel == 0 ? 1 : sel == 1 ? 2 : sel == 2 ? 4 : 5);
    const float* Xb = X + (size_t)b * Nn * ldx;
    float* Zbh = Zh + (size_t)b * Nn * ldz + (size_t)slice * fin;
    float* Zbl = Zl + (size_t)b * Nn * ldz + (size_t)slice * fin;

    __shared__ float Ah[16][136], Al[16][136];
    __shared__ float Bh[16][72],  Bl[16][72];

    const int tid  = threadIdx.x;
    const int warp = tid >> 5, lane = tid & 31;
    const int wm = warp >> 1, wn = warp & 1;
    const int g  = lane >> 2, tg = lane & 3;
    const int bn = blockIdx.x * 64;

    const int ar = tid >> 1;
    const int acol = (tid & 1) * 8;
    const int br = tid >> 4;
    const int bc = (tid & 15) * 4;

    float acc[2][4][4] = {};
    float4 Areg0, Areg1, Breg;
    {
        const float* Ap = G + (size_t)ar * Nn + acol;
        Areg0 = *(const float4*)(Ap);
        Areg1 = *(const float4*)(Ap + 4);
        Breg  = *(const float4*)(Xb + (size_t)br * ldx + bn + bc);
    }

    for (int t = 0; t < 8; t++) {
        {
            const float* av0 = (const float*)&Areg0;
            const float* av1 = (const float*)&Areg1;
            #pragma unroll
            for (int e = 0; e < 4; e++) {
                float x = av0[e]; float h = to_tf32(x);
                Ah[acol + e][ar] = h; Al[acol + e][ar] = to_tf32(x - h);
            }
            #pragma unroll
            for (int e = 0; e < 4; e++) {
                float x = av1[e]; float h = to_tf32(x);
                Ah[acol + 4 + e][ar] = h; Al[acol + 4 + e][ar] = to_tf32(x - h);
            }
            float4 h4, l4;
            const float* bv = (const float*)&Breg;
            float* hp = (float*)&h4; float* lp = (float*)&l4;
            #pragma unroll
            for (int e = 0; e < 4; e++) {
                float x = bv[e]; float h = to_tf32(x);
                hp[e] = h; lp[e] = to_tf32(x - h);
            }
            *(float4*)&Bh[br][bc] = h4;
            *(float4*)&Bl[br][bc] = l4;
        }
        __syncthreads();

        if (t + 1 < 8) {
            int k0 = (t + 1) * 16;
            const float* Ap = G + (size_t)ar * Nn + k0 + acol;
            Areg0 = *(const float4*)(Ap);
            Areg1 = *(const float4*)(Ap + 4);
            Breg  = *(const float4*)(Xb + (size_t)(k0 + br) * ldx + bn + bc);
        }

        #pragma unroll
        for (int kb = 0; kb < 16; kb += 8) {
            uint32_t ahi[2][4], alo[2][4];
            #pragma unroll
            for (int mt = 0; mt < 2; mt++) {
                int m0 = wm * 32 + mt * 16 + g;
                ahi[mt][0] = __float_as_uint(Ah[kb + tg][m0]);
                ahi[mt][1] = __float_as_uint(Ah[kb + tg][m0 + 8]);
                ahi[mt][2] = __float_as_uint(Ah[kb + tg + 4][m0]);
                ahi[mt][3] = __float_as_uint(Ah[kb + tg + 4][m0 + 8]);
                alo[mt][0] = __float_as_uint(Al[kb + tg][m0]);
                alo[mt][1] = __float_as_uint(Al[kb + tg][m0 + 8]);
                alo[mt][2] = __float_as_uint(Al[kb + tg + 4][m0]);
                alo[mt][3] = __float_as_uint(Al[kb + tg + 4][m0 + 8]);
            }
            uint32_t bhi[4][2], blo[4][2];
            #pragma unroll
            for (int nt = 0; nt < 4; nt++) {
                int n0 = wn * 32 + nt * 8 + g;
                bhi[nt][0] = __float_as_uint(Bh[kb + tg][n0]);
                bhi[nt][1] = __float_as_uint(Bh[kb + tg + 4][n0]);
                blo[nt][0] = __float_as_uint(Bl[kb + tg][n0]);
                blo[nt][1] = __float_as_uint(Bl[kb + tg + 4][n0]);
            }
            #pragma unroll
            for (int mt = 0; mt < 2; mt++)
                #pragma unroll
                for (int nt = 0; nt < 4; nt++) {
                    mma_tf32(acc[mt][nt], ahi[mt][0], ahi[mt][1], ahi[mt][2], ahi[mt][3],
                             bhi[nt][0], bhi[nt][1]);
                    mma_tf32(acc[mt][nt], ahi[mt][0], ahi[mt][1], ahi[mt][2], ahi[mt][3],
                             blo[nt][0], blo[nt][1]);
                    mma_tf32(acc[mt][nt], alo[mt][0], alo[mt][1], alo[mt][2], alo[mt][3],
                             bhi[nt][0], bhi[nt][1]);
                }
        }
        __syncthreads();
    }

    #pragma unroll
    for (int mt = 0; mt < 2; mt++) {
        int r0 = wm * 32 + mt * 16 + g;
        int r1 = r0 + 8;
        #pragma unroll
        for (int nt = 0; nt < 4; nt++) {
            #pragma unroll
            for (int c = 0; c < 2; c++) {
                int n = bn + wn * 32 + nt * 8 + tg * 2 + c;
                float v0 = acc[mt][nt][c], v1 = acc[mt][nt][2 + c];
                float h0 = to_tf32(v0), h1 = to_tf32(v1);
                Zbh[(size_t)r0 * ldz + n] = h0;
                Zbl[(size_t)r0 * ldz + n] = to_tf32(v0 - h0);
                Zbh[(size_t)r1 * ldz + n] = h1;
                Zbl[(size_t)r1 * ldz + n] = to_tf32(v1 - h1);
            }
        }
    }
}

// ---------------- fused U+V projection ----------------
__global__ __launch_bounds__(256) void uv_proj(
    const float* __restrict__ x, const float* __restrict__ eW1,
    float* __restrict__ U, float* __restrict__ V)
{
    __shared__ float xs[32][132];
    __shared__ float Wu[16][64], Wv[16][64];

    const int tid = threadIdx.x;
    const int base = blockIdx.x * 32;

    #pragma unroll
    for (int i = tid; i < 32 * 32; i += 256) {
        int r = i >> 5, c4 = (i & 31) * 4;
        float4 v = *(const float4*)(x + (size_t)(base + r) * 128 + c4);
        *(float4*)&xs[r][c4] = v;
    }

    const int tx = tid & 15;
    const int ty = tid >> 4;
    float aU[2][4] = {}, aV[2][4] = {};

    for (int k0 = 0; k0 < 128; k0 += 16) {
        #pragma unroll
        for (int i = tid; i < 16 * 16; i += 256) {
            int kk = i >> 4, c4 = (i & 15) * 4;
            *(float4*)&Wu[kk][c4] = *(const float4*)(eW1 + (size_t)(k0 + kk) * 64 + c4);
            *(float4*)&Wv[kk][c4] = *(const float4*)(eW1 + (size_t)(128 + k0 + kk) * 64 + c4);
        }
        __syncthreads();
        #pragma unroll
        for (int k = 0; k < 16; k++) {
            float4 wu = *(const float4*)&Wu[k][tx * 4];
            float4 wv = *(const float4*)&Wv[k][tx * 4];
            #pragma unroll
            for (int r = 0; r < 2; r++) {
                float a = xs[ty * 2 + r][k0 + k];
                aU[r][0] += a * wu.x; aU[r][1] += a * wu.y;
                aU[r][2] += a * wu.z; aU[r][3] += a * wu.w;
                aV[r][0] += a * wv.x; aV[r][1] += a * wv.y;
                aV[r][2] += a * wv.z; aV[r][3] += a * wv.w;
            }
        }
        __syncthreads();
    }

    #pragma unroll
    for (int r = 0; r < 2; r++) {
        size_t row = (size_t)(base + ty * 2 + r) * 64 + tx * 4;
        *(float4*)(U + row) = make_float4(aU[r][0], aU[r][1], aU[r][2], aU[r][3]);
        *(float4*)(V + row) = make_float4(aV[r][0], aV[r][1], aV[r][2], aV[r][3]);
    }
}

// ---------------- edge scorer ----------------
__global__ void edge_scores(const float* __restrict__ U, const float* __restrict__ V,
                            const float* __restrict__ eb1, const float* __restrict__ eW2,
                            const float* __restrict__ eb2, float* __restrict__ S)
{
    int b = blockIdx.z;
    int i0 = blockIdx.y * 32, j0 = blockIdx.x * 32;
    __shared__ float Ush[32][65], Vsh[32][65];
    __shared__ float w2[64], b1[64];
    int tid = threadIdx.x;
    if (tid < 64) { w2[tid] = eW2[tid]; b1[tid] = eb1[tid]; }
    for (int idx = tid; idx < 32 * 64; idx += 256) {
        int r = idx >> 6, h = idx & 63;
        Ush[r][h] = U[((size_t)b * Nn + i0 + r) * 64 + h];
        Vsh[r][h] = V[((size_t)b * Nn + j0 + r) * 64 + h];
    }
    __syncthreads();
    int tx = tid & 31;
    int ty = tid >> 5;
    float acc[4] = {0, 0, 0, 0};
    for (int h = 0; h < 64; h++) {
        float vj = Vsh[tx][h];
        float wb = w2[h], bb = b1[h];
        #pragma unroll
        for (int r = 0; r < 4; r++) {
            float t = Ush[ty * 4 + r][h] + vj + bb;
            acc[r] += fmaxf(t, 0.0f) * wb;
        }
    }
    float e2 = eb2[0];
    #pragma unroll
    for (int r = 0; r < 4; r++)
        S[((size_t)b * Nn + i0 + ty * 4 + r) * Nn + j0 + tx] = acc[r] + e2;
}

// AP = masked strict-upper exp(0.5*(S+S^T)); RS = row sums (0 -> 1)
__global__ void ap_rowsum(const float* __restrict__ S, const float* __restrict__ mask,
                          float* __restrict__ AP, float* __restrict__ RS)
{
    int bi = blockIdx.x;
    int b = bi >> 7, i = bi & 127;
    int j = threadIdx.x;
    float v = 0.0f;
    if (j > i) {
        float mm = mask[b * Nn + i] * mask[b * Nn + j];
        if (mm != 0.0f)
            v = expf(0.5f * (S[(size_t)bi * Nn + j] + S[((size_t)b * Nn + j) * Nn + i]));
    }
    AP[(size_t)bi * Nn + j] = v;
    __shared__ float red[128];
    red[j] = v;
    __syncthreads();
    for (int s = 64; s > 0; s >>= 1) {
        if (j < s) red[j] += red[j + s];
        __syncthreads();
    }
    if (j == 0) { float rs = red[0]; RS[bi] = (rs == 0.0f) ? 1.0f : rs; }
}

__global__ void build_An(const float* __restrict__ AP, const float* __restrict__ RS,
                         float* __restrict__ An)
{
    int bi = blockIdx.x;
    int b = bi >> 7, i = bi & 127;
    int j = threadIdx.x;
    An[(size_t)bi * Nn + j] = AP[(size_t)bi * Nn + j] / RS[bi]
                            + AP[((size_t)b * Nn + j) * Nn + i] / RS[b * Nn + j];
}

// Fused degree + normalized Laplacian
__global__ void degree_build_L(const float* __restrict__ M, float* __restrict__ L)
{
    int b = blockIdx.x;
    int j = threadIdx.x;
    const float* Mb = M + (size_t)b * Nn * Nn;
    float* Lb = L + (size_t)b * Nn * Nn;
    __shared__ float Dsh[Nn];
    float s = 0.0f;
    for (int i = 0; i < Nn; i++) s += Mb[(size_t)i * Nn + j];
    float dj = 1.0f / sqrtf(s + 1e-5f);
    Dsh[j] = dj;
    __syncthreads();
    for (int i = 0; i < Nn; i++)
        Lb[(size_t)i * Nn + j] = Dsh[i] * Mb[(size_t)i * Nn + j] * dj;
}

// write X split hi/lo into Z columns [0,fin) and [3fin,4fin)
__global__ void copy_xz(const float* __restrict__ X,
                        float* __restrict__ Zh, float* __restrict__ Zl,
                        int fin, int ldz)
{
    int r = blockIdx.x;
    for (int c = threadIdx.x; c < fin; c += blockDim.x) {
        float v = X[(size_t)r * fin + c];
        float h = to_tf32(v);
        float l = to_tf32(v - h);
        Zh[(size_t)r * ldz + c] = h;
        Zl[(size_t)r * ldz + c] = l;
        Zh[(size_t)r * ldz + 3 * fin + c] = h;
        Zl[(size_t)r * ldz + 3 * fin + c] = l;
    }
}

// Fused maxpool + classifier head
__global__ void pool_classifier(const float* __restrict__ H,
                                const float* __restrict__ fW1, const float* __restrict__ fb1,
                                const float* __restrict__ fW2, const float* __restrict__ fb2,
                                float* __restrict__ out)
{
    int b = blockIdx.x;
    int tid = threadIdx.x;  // 512 threads
    __shared__ float sp[512];
    __shared__ float st[256];
    {
        float m = -3.4e38f;
        const float* Hb = H + (size_t)b * Nn * 512 + tid;
        for (int n = 0; n < Nn; n++)
            m = fmaxf(m, Hb[(size_t)n * 512]);
        sp[tid] = m;
    }
    __syncthreads();
    if (tid < 256) {
        float t = fb1[tid];
        for (int k = 0; k < 512; k++) t += sp[k] * fW1[k * 256 + tid];
        st[tid] = t;
    }
    __syncthreads();
    if (tid < 10) {
        float o = fb2[tid];
        for (int h = 0; h < 256; h++) o += st[h] * fW2[h * 10 + tid];
        out[b * 10 + tid] = o;
    }
}

// ---------------- driver ----------------
extern "C" void kernel_launch(void* const* d_in, const int* in_sizes, int n_in,
                              void* d_out, int out_size)
{
    const float* x    = (const float*)d_in[0];
    const float* A    = (const float*)d_in[1];
    const float* mask = (const float*)d_in[2];
    const float* eW1  = (const float*)d_in[3];
    const float* eb1  = (const float*)d_in[4];
    const float* eW2  = (const float*)d_in[5];
    const float* eb2  = (const float*)d_in[6];
    const float* gW[3], *gb[3], *gg[3], *gbe[3], *gm[3], *gv[3];
    for (int li = 0; li < 3; li++) {
        int base = 7 + li * 6;
        gW[li]  = (const float*)d_in[base + 0];
        gb[li]  = (const float*)d_in[base + 1];
        gg[li]  = (const float*)d_in[base + 2];
        gbe[li] = (const float*)d_in[base + 3];
        gm[li]  = (const float*)d_in[base + 4];
        gv[li]  = (const float*)d_in[base + 5];
    }
    const float* fW1 = (const float*)d_in[25];
    const float* fb1 = (const float*)d_in[26];
    const float* fW2 = (const float*)d_in[27];
    const float* fb2 = (const float*)d_in[28];

    float* buf = nullptr;
    cudaGetSymbolAddress((void**)&buf, g_buf);
    float* U  = buf + OFF_U;
    float* V  = buf + OFF_V;
    float* S  = buf + OFF_S;
    float* AP = buf + OFF_AP;
    float* RS = buf + OFF_RS;
    float* An = buf + OFF_AN;
    float* L0 = buf + OFF_L0;
    float* L1 = buf + OFF_L1;
    float* M0 = buf + OFF_M0;
    float* M1 = buf + OFF_M1;
    float* Zh = buf + OFF_ZH;
    float* Zl = buf + OFF_ZL;
    float* Hb[3] = { buf + OFF_H0, buf + OFF_H1, buf + OFF_H2 };

    // edge adjacency path
    uv_proj<<<128, 256>>>(x, eW1, U, V);
    edge_scores<<<dim3(4, 4, Bsz), 256>>>(U, V, eb1, eW2, eb2, S);
    ap_rowsum<<<Bsz * Nn, 128>>>(S, mask, AP, RS);
    build_An<<<Bsz * Nn, 128>>>(AP, RS, An);
    degree_build_L<<<Bsz, 128>>>(A, L0);
    degree_build_L<<<Bsz, 128>>>(An, L1);
    build_M<<<dim3(2, 1, 2 * Bsz), 256>>>(L0, L1, M0, M1);

    // 3 graph-conv layers
    const float* Xin = x;
    int fin = 128;
    int fouts[3] = { 64, 256, 512 };
    for (int li = 0; li < 3; li++) {
        int ldz = 6 * fin;
        copy_xz<<<Bsz * Nn, 128>>>(Xin, Zh, Zl, fin, ldz);
        cheb_tc<<<dim3(fin / 64, 1, 4 * Bsz), 256>>>(L0, M0, L1, M1, Xin, fin,
                                                     Zh, Zl, ldz, fin);
        int fo = fouts[li];
        gemm_tc<<<dim3(fo / 64, 32), 256>>>(Zh, Zl, ldz, gW[li], fo, Hb[li], fo, 6 * fin,
                                            gb[li], mask, gg[li], gbe[li], gm[li], gv[li]);
        Xin = Hb[li];
        fin = fo;
    }

    pool_classifier<<<Bsz, 512>>>(Hb[2], fW1, fb1, fW2, fb2, (float*)d_out);
}

// round 15
// speedup vs baseline: 1.1271x; 1.1271x over previous
#include <cuda_runtime.h>
#include <math.h>
#include <stdint.h>

#define Bsz 32
#define Nn  128
#define Cc  128

// ---------------- scratch ----------------
constexpr size_t OFF_U  = 0;
constexpr size_t OFF_V  = OFF_U  + (size_t)Bsz*Nn*64;
constexpr size_t OFF_S  = OFF_V  + (size_t)Bsz*Nn*64;
constexpr size_t OFF_AP = OFF_S  + (size_t)Bsz*Nn*Nn;
constexpr size_t OFF_RS = OFF_AP + (size_t)Bsz*Nn*Nn;
constexpr size_t OFF_AN = OFF_RS + (size_t)Bsz*Nn;
constexpr size_t OFF_L0 = OFF_AN + (size_t)Bsz*Nn*Nn;
constexpr size_t OFF_L1 = OFF_L0 + (size_t)Bsz*Nn*Nn;
constexpr size_t OFF_M0 = OFF_L1 + (size_t)Bsz*Nn*Nn;
constexpr size_t OFF_M1 = OFF_M0 + (size_t)Bsz*Nn*Nn;
constexpr size_t OFF_Z  = OFF_M1 + (size_t)Bsz*Nn*Nn;
constexpr size_t OFF_H0 = OFF_Z  + (size_t)Bsz*Nn*1536;
constexpr size_t OFF_H1 = OFF_H0 + (size_t)Bsz*Nn*64;
constexpr size_t OFF_H2 = OFF_H1 + (size_t)Bsz*Nn*256;
constexpr size_t TOTAL_F = OFF_H2 + (size_t)Bsz*Nn*512;

__device__ float g_buf[TOTAL_F];

// ---------------- tf32 helpers ----------------
__device__ __forceinline__ float to_tf32(float x) {
    float r;
    asm("cvt.rna.tf32.f32 %0, %1;" : "=f"(r) : "f"(x));
    return r;
}

__device__ __forceinline__ void mma_tf32(float* d,
                                         uint32_t a0, uint32_t a1, uint32_t a2, uint32_t a3,
                                         uint32_t b0, uint32_t b1) {
    asm volatile(
        "mma.sync.aligned.m16n8k8.row.col.f32.tf32.tf32.f32 "
        "{%0,%1,%2,%3}, {%4,%5,%6,%7}, {%8,%9}, {%0,%1,%2,%3};"
        : "+f"(d[0]), "+f"(d[1]), "+f"(d[2]), "+f"(d[3])
        : "r"(a0), "r"(a1), "r"(a2), "r"(a3), "r"(b0), "r"(b1));
}

// ---------------- 3xTF32 dense GEMM with fused BN epilogue (R10-proven + occ=2) ----------------
// C[M,Nc] = A[M,K] @ B[K,Nc]; block tile 128x64, grid = (Nc/64, M/128).
__global__ __launch_bounds__(256, 2) void gemm_tc(
    const float* __restrict__ A, int lda,
    const float* __restrict__ B, int ldb,
    float* __restrict__ C, int ldc, int K,
    const float* __restrict__ bias,
    const float* __restrict__ rowmask,
    const float* __restrict__ bng, const float* __restrict__ bnb,
    const float* __restrict__ bnm, const float* __restrict__ bnv)
{
    __shared__ float Ah[16][136], Al[16][136];
    __shared__ float Bh[16][72],  Bl[16][72];

    const int tid  = threadIdx.x;
    const int warp = tid >> 5, lane = tid & 31;
    const int wm = warp >> 1, wn = warp & 1;
    const int g  = lane >> 2, tg = lane & 3;

    const int bm = blockIdx.y * 128, bn = blockIdx.x * 64;

    const int ar = tid >> 1;
    const int acol = (tid & 1) * 8;
    const int br = tid >> 4;
    const int bc = (tid & 15) * 4;

    float acc[2][4][4] = {};
    float4 Areg0, Areg1, Breg;

    const int nkt = K / 16;
    {
        const float* Ap = A + (size_t)(bm + ar) * lda + acol;
        Areg0 = *(const float4*)(Ap);
        Areg1 = *(const float4*)(Ap + 4);
        Breg  = *(const float4*)(B + (size_t)br * ldb + bn + bc);
    }

    for (int t = 0; t < nkt; t++) {
        {
            const float* av0 = (const float*)&Areg0;
            const float* av1 = (const float*)&Areg1;
            #pragma unroll
            for (int e = 0; e < 4; e++) {
                float x = av0[e];
                float h = to_tf32(x);
                Ah[acol + e][ar] = h;
                Al[acol + e][ar] = to_tf32(x - h);
            }
            #pragma unroll
            for (int e = 0; e < 4; e++) {
                float x = av1[e];
                float h = to_tf32(x);
                Ah[acol + 4 + e][ar] = h;
                Al[acol + 4 + e][ar] = to_tf32(x - h);
            }
            float4 h4, l4;
            const float* bv = (const float*)&Breg;
            float* hp = (float*)&h4; float* lp = (float*)&l4;
            #pragma unroll
            for (int e = 0; e < 4; e++) {
                float x = bv[e];
                float h = to_tf32(x);
                hp[e] = h; lp[e] = to_tf32(x - h);
            }
            *(float4*)&Bh[br][bc] = h4;
            *(float4*)&Bl[br][bc] = l4;
        }
        __syncthreads();

        if (t + 1 < nkt) {
            int k0 = (t + 1) * 16;
            const float* Ap = A + (size_t)(bm + ar) * lda + k0 + acol;
            Areg0 = *(const float4*)(Ap);
            Areg1 = *(const float4*)(Ap + 4);
            Breg  = *(const float4*)(B + (size_t)(k0 + br) * ldb + bn + bc);
        }

        #pragma unroll
        for (int kb = 0; kb < 16; kb += 8) {
            uint32_t ahi[2][4], alo[2][4];
            #pragma unroll
            for (int mt = 0; mt < 2; mt++) {
                int m0 = wm * 32 + mt * 16 + g;
                ahi[mt][0] = __float_as_uint(Ah[kb + tg][m0]);
                ahi[mt][1] = __float_as_uint(Ah[kb + tg][m0 + 8]);
                ahi[mt][2] = __float_as_uint(Ah[kb + tg + 4][m0]);
                ahi[mt][3] = __float_as_uint(Ah[kb + tg + 4][m0 + 8]);
                alo[mt][0] = __float_as_uint(Al[kb + tg][m0]);
                alo[mt][1] = __float_as_uint(Al[kb + tg][m0 + 8]);
                alo[mt][2] = __float_as_uint(Al[kb + tg + 4][m0]);
                alo[mt][3] = __float_as_uint(Al[kb + tg + 4][m0 + 8]);
            }
            uint32_t bhi[4][2], blo[4][2];
            #pragma unroll
            for (int nt = 0; nt < 4; nt++) {
                int n0 = wn * 32 + nt * 8 + g;
                bhi[nt][0] = __float_as_uint(Bh[kb + tg][n0]);
                bhi[nt][1] = __float_as_uint(Bh[kb + tg + 4][n0]);
                blo[nt][0] = __float_as_uint(Bl[kb + tg][n0]);
                blo[nt][1] = __float_as_uint(Bl[kb + tg + 4][n0]);
            }
            #pragma unroll
            for (int mt = 0; mt < 2; mt++)
                #pragma unroll
                for (int nt = 0; nt < 4; nt++) {
                    mma_tf32(acc[mt][nt], ahi[mt][0], ahi[mt][1], ahi[mt][2], ahi[mt][3],
                             bhi[nt][0], bhi[nt][1]);
                    mma_tf32(acc[mt][nt], ahi[mt][0], ahi[mt][1], ahi[mt][2], ahi[mt][3],
                             blo[nt][0], blo[nt][1]);
                    mma_tf32(acc[mt][nt], alo[mt][0], alo[mt][1], alo[mt][2], alo[mt][3],
                             bhi[nt][0], bhi[nt][1]);
                }
        }
        __syncthreads();
    }

    #pragma unroll
    for (int mt = 0; mt < 2; mt++) {
        int r0 = bm + wm * 32 + mt * 16 + g;
        int r1 = r0 + 8;
        float mk0 = rowmask[r0], mk1 = rowmask[r1];
        #pragma unroll
        for (int nt = 0; nt < 4; nt++) {
            #pragma unroll
            for (int c = 0; c < 2; c++) {
                int n = bn + wn * 32 + nt * 8 + tg * 2 + c;
                float sc = bng[n] / sqrtf(bnv[n] + 1e-5f);
                float mu = bnm[n], bb = bnb[n], bi = bias[n];
                float v0 = (acc[mt][nt][c]     + bi) * mk0;
                float v1 = (acc[mt][nt][2 + c] + bi) * mk1;
                v0 = fmaxf((v0 - mu) * sc + bb, 0.0f);
                v1 = fmaxf((v1 - mu) * sc + bb, 0.0f);
                C[(size_t)r0 * ldc + n] = v0;
                C[(size_t)r1 * ldc + n] = v1;
            }
        }
    }
}

// ---------------- batched M = 2*L@L - I (3xTF32) ----------------
__global__ __launch_bounds__(256, 2) void build_M(
    const float* __restrict__ L0, const float* __restrict__ L1,
    float* __restrict__ M0, float* __restrict__ M1)
{
    const int z = blockIdx.z;
    const int b = z & (Bsz - 1);
    const float* Lb = (z < Bsz ? L0 : L1) + (size_t)b * Nn * Nn;
    float* Mb = (z < Bsz ? M0 : M1) + (size_t)b * Nn * Nn;

    __shared__ float Ah[16][136], Al[16][136];
    __shared__ float Bh[16][72],  Bl[16][72];

    const int tid  = threadIdx.x;
    const int warp = tid >> 5, lane = tid & 31;
    const int wm = warp >> 1, wn = warp & 1;
    const int g  = lane >> 2, tg = lane & 3;
    const int bn = blockIdx.x * 64;

    const int ar = tid >> 1;
    const int acol = (tid & 1) * 8;
    const int br = tid >> 4;
    const int bc = (tid & 15) * 4;

    float acc[2][4][4] = {};
    float4 Areg0, Areg1, Breg;
    {
        const float* Ap = Lb + (size_t)ar * Nn + acol;
        Areg0 = *(const float4*)(Ap);
        Areg1 = *(const float4*)(Ap + 4);
        Breg  = *(const float4*)(Lb + (size_t)br * Nn + bn + bc);
    }

    for (int t = 0; t < 8; t++) {
        {
            const float* av0 = (const float*)&Areg0;
            const float* av1 = (const float*)&Areg1;
            #pragma unroll
            for (int e = 0; e < 4; e++) {
                float x = av0[e]; float h = to_tf32(x);
                Ah[acol + e][ar] = h; Al[acol + e][ar] = to_tf32(x - h);
            }
            #pragma unroll
            for (int e = 0; e < 4; e++) {
                float x = av1[e]; float h = to_tf32(x);
                Ah[acol + 4 + e][ar] = h; Al[acol + 4 + e][ar] = to_tf32(x - h);
            }
            float4 h4, l4;
            const float* bv = (const float*)&Breg;
            float* hp = (float*)&h4; float* lp = (float*)&l4;
            #pragma unroll
            for (int e = 0; e < 4; e++) {
                float x = bv[e]; float h = to_tf32(x);
                hp[e] = h; lp[e] = to_tf32(x - h);
            }
            *(float4*)&Bh[br][bc] = h4;
            *(float4*)&Bl[br][bc] = l4;
        }
        __syncthreads();

        if (t + 1 < 8) {
            int k0 = (t + 1) * 16;
            const float* Ap = Lb + (size_t)ar * Nn + k0 + acol;
            Areg0 = *(const float4*)(Ap);
            Areg1 = *(const float4*)(Ap + 4);
            Breg  = *(const float4*)(Lb + (size_t)(k0 + br) * Nn + bn + bc);
        }

        #pragma unroll
        for (int kb = 0; kb < 16; kb += 8) {
            uint32_t ahi[2][4], alo[2][4];
            #pragma unroll
            for (int mt = 0; mt < 2; mt++) {
                int m0 = wm * 32 + mt * 16 + g;
                ahi[mt][0] = __float_as_uint(Ah[kb + tg][m0]);
                ahi[mt][1] = __float_as_uint(Ah[kb + tg][m0 + 8]);
                ahi[mt][2] = __float_as_uint(Ah[kb + tg + 4][m0]);
                ahi[mt][3] = __float_as_uint(Ah[kb + tg + 4][m0 + 8]);
                alo[mt][0] = __float_as_uint(Al[kb + tg][m0]);
                alo[mt][1] = __float_as_uint(Al[kb + tg][m0 + 8]);
                alo[mt][2] = __float_as_uint(Al[kb + tg + 4][m0]);
                alo[mt][3] = __float_as_uint(Al[kb + tg + 4][m0 + 8]);
            }
            uint32_t bhi[4][2], blo[4][2];
            #pragma unroll
            for (int nt = 0; nt < 4; nt++) {
                int n0 = wn * 32 + nt * 8 + g;
                bhi[nt][0] = __float_as_uint(Bh[kb + tg][n0]);
                bhi[nt][1] = __float_as_uint(Bh[kb + tg + 4][n0]);
                blo[nt][0] = __float_as_uint(Bl[kb + tg][n0]);
                blo[nt][1] = __float_as_uint(Bl[kb + tg + 4][n0]);
            }
            #pragma unroll
            for (int mt = 0; mt < 2; mt++)
                #pragma unroll
                for (int nt = 0; nt < 4; nt++) {
                    mma_tf32(acc[mt][nt], ahi[mt][0], ahi[mt][1], ahi[mt][2], ahi[mt][3],
                             bhi[nt][0], bhi[nt][1]);
                    mma_tf32(acc[mt][nt], ahi[mt][0], ahi[mt][1], ahi[mt][2], ahi[mt][3],
                             blo[nt][0], blo[nt][1]);
                    mma_tf32(acc[mt][nt], alo[mt][0], alo[mt][1], alo[mt][2], alo[mt][3],
                             bhi[nt][0], bhi[nt][1]);
                }
        }
        __syncthreads();
    }

    #pragma unroll
    for (int mt = 0; mt < 2; mt++) {
        int r0 = wm * 32 + mt * 16 + g;
        int r1 = r0 + 8;
        #pragma unroll
        for (int nt = 0; nt < 4; nt++) {
            #pragma unroll
            for (int c = 0; c < 2; c++) {
                int n = bn + wn * 32 + nt * 8 + tg * 2 + c;
                float v0 = 2.0f * acc[mt][nt][c]     - (r0 == n ? 1.0f : 0.0f);
                float v1 = 2.0f * acc[mt][nt][2 + c] - (r1 == n ? 1.0f : 0.0f);
                Mb[(size_t)r0 * Nn + n] = v0;
                Mb[(size_t)r1 * Nn + n] = v1;
            }
        }
    }
}

// ---------------- batched Chebyshev products into Z slices (3xTF32) ----------------
// grid: (fin/64, 1, 4*Bsz). sel = z>>5: 0->L0 s1, 1->M0 s2, 2->L1 s4, 3->M1 s5.
__global__ __launch_bounds__(256, 2) void cheb_tc(
    const float* __restrict__ L0, const float* __restrict__ M0,
    const float* __restrict__ L1, const float* __restrict__ M1,
    const float* __restrict__ X, int ldx,
    float* __restrict__ Z, int ldz, int fin)
{
    const int z = blockIdx.z;
    const int b = z & (Bsz - 1);
    const int sel = z >> 5;
    const float* G = (sel == 0 ? L0 : sel == 1 ? M0 : sel == 2 ? L1 : M1)
                     + (size_t)b * Nn * Nn;
    const int slice = (sel == 0 ? 1 : sel == 1 ? 2 : sel == 2 ? 4 : 5);
    const float* Xb = X + (size_t)b * Nn * ldx;
    float* Zb = Z + (size_t)b * Nn * ldz + (size_t)slice * fin;

    __shared__ float Ah[16][136], Al[16][136];
    __shared__ float Bh[16][72],  Bl[16][72];

    const int tid  = threadIdx.x;
    const int warp = tid >> 5, lane = tid & 31;
    const int wm = warp >> 1, wn = warp & 1;
    const int g  = lane >> 2, tg = lane & 3;
    const int bn = blockIdx.x * 64;

    const int ar = tid >> 1;
    const int acol = (tid & 1) * 8;
    const int br = tid >> 4;
    const int bc = (tid & 15) * 4;

    float acc[2][4][4] = {};
    float4 Areg0, Areg1, Breg;
    {
        const float* Ap = G + (size_t)ar * Nn + acol;
        Areg0 = *(const float4*)(Ap);
        Areg1 = *(const float4*)(Ap + 4);
        Breg  = *(const float4*)(Xb + (size_t)br * ldx + bn + bc);
    }

    for (int t = 0; t < 8; t++) {
        {
            const float* av0 = (const float*)&Areg0;
            const float* av1 = (const float*)&Areg1;
            #pragma unroll
            for (int e = 0; e < 4; e++) {
                float x = av0[e]; float h = to_tf32(x);
                Ah[acol + e][ar] = h; Al[acol + e][ar] = to_tf32(x - h);
            }
            #pragma unroll
            for (int e = 0; e < 4; e++) {
                float x = av1[e]; float h = to_tf32(x);
                Ah[acol + 4 + e][ar] = h; Al[acol + 4 + e][ar] = to_tf32(x - h);
            }
            float4 h4, l4;
            const float* bv = (const float*)&Breg;
            float* hp = (float*)&h4; float* lp = (float*)&l4;
            #pragma unroll
            for (int e = 0; e < 4; e++) {
                float x = bv[e]; float h = to_tf32(x);
                hp[e] = h; lp[e] = to_tf32(x - h);
            }
            *(float4*)&Bh[br][bc] = h4;
            *(float4*)&Bl[br][bc] = l4;
        }
        __syncthreads();

        if (t + 1 < 8) {
            int k0 = (t + 1) * 16;
            const float* Ap = G + (size_t)ar * Nn + k0 + acol;
            Areg0 = *(const float4*)(Ap);
            Areg1 = *(const float4*)(Ap + 4);
            Breg  = *(const float4*)(Xb + (size_t)(k0 + br) * ldx + bn + bc);
        }

        #pragma unroll
        for (int kb = 0; kb < 16; kb += 8) {
            uint32_t ahi[2][4], alo[2][4];
            #pragma unroll
            for (int mt = 0; mt < 2; mt++) {
                int m0 = wm * 32 + mt * 16 + g;
                ahi[mt][0] = __float_as_uint(Ah[kb + tg][m0]);
                ahi[mt][1] = __float_as_uint(Ah[kb + tg][m0 + 8]);
                ahi[mt][2] = __float_as_uint(Ah[kb + tg + 4][m0]);
                ahi[mt][3] = __float_as_uint(Ah[kb + tg + 4][m0 + 8]);
                alo[mt][0] = __float_as_uint(Al[kb + tg][m0]);
                alo[mt][1] = __float_as_uint(Al[kb + tg][m0 + 8]);
                alo[mt][2] = __float_as_uint(Al[kb + tg + 4][m0]);
                alo[mt][3] = __float_as_uint(Al[kb + tg + 4][m0 + 8]);
            }
            uint32_t bhi[4][2], blo[4][2];
            #pragma unroll
            for (int nt = 0; nt < 4; nt++) {
                int n0 = wn * 32 + nt * 8 + g;
                bhi[nt][0] = __float_as_uint(Bh[kb + tg][n0]);
                bhi[nt][1] = __float_as_uint(Bh[kb + tg + 4][n0]);
                blo[nt][0] = __float_as_uint(Bl[kb + tg][n0]);
                blo[nt][1] = __float_as_uint(Bl[kb + tg + 4][n0]);
            }
            #pragma unroll
            for (int mt = 0; mt < 2; mt++)
                #pragma unroll
                for (int nt = 0; nt < 4; nt++) {
                    mma_tf32(acc[mt][nt], ahi[mt][0], ahi[mt][1], ahi[mt][2], ahi[mt][3],
                             bhi[nt][0], bhi[nt][1]);
                    mma_tf32(acc[mt][nt], ahi[mt][0], ahi[mt][1], ahi[mt][2], ahi[mt][3],
                             blo[nt][0], blo[nt][1]);
                    mma_tf32(acc[mt][nt], alo[mt][0], alo[mt][1], alo[mt][2], alo[mt][3],
                             bhi[nt][0], bhi[nt][1]);
                }
        }
        __syncthreads();
    }

    #pragma unroll
    for (int mt = 0; mt < 2; mt++) {
        int r0 = wm * 32 + mt * 16 + g;
        int r1 = r0 + 8;
        #pragma unroll
        for (int nt = 0; nt < 4; nt++) {
            #pragma unroll
            for (int c = 0; c < 2; c++) {
                int n = bn + wn * 32 + nt * 8 + tg * 2 + c;
                Zb[(size_t)r0 * ldz + n] = acc[mt][nt][c];
                Zb[(size_t)r1 * ldz + n] = acc[mt][nt][2 + c];
            }
        }
    }
}

// ---------------- fused U+V projection ----------------
__global__ __launch_bounds__(256) void uv_proj(
    const float* __restrict__ x, const float* __restrict__ eW1,
    float* __restrict__ U, float* __restrict__ V)
{
    __shared__ float xs[32][132];
    __shared__ float Wu[16][64], Wv[16][64];

    const int tid = threadIdx.x;
    const int base = blockIdx.x * 32;

    #pragma unroll
    for (int i = tid; i < 32 * 32; i += 256) {
        int r = i >> 5, c4 = (i & 31) * 4;
        float4 v = *(const float4*)(x + (size_t)(base + r) * 128 + c4);
        *(float4*)&xs[r][c4] = v;
    }

    const int tx = tid & 15;
    const int ty = tid >> 4;
    float aU[2][4] = {}, aV[2][4] = {};

    for (int k0 = 0; k0 < 128; k0 += 16) {
        #pragma unroll
        for (int i = tid; i < 16 * 16; i += 256) {
            int kk = i >> 4, c4 = (i & 15) * 4;
            *(float4*)&Wu[kk][c4] = *(const float4*)(eW1 + (size_t)(k0 + kk) * 64 + c4);
            *(float4*)&Wv[kk][c4] = *(const float4*)(eW1 + (size_t)(128 + k0 + kk) * 64 + c4);
        }
        __syncthreads();
        #pragma unroll
        for (int k = 0; k < 16; k++) {
            float4 wu = *(const float4*)&Wu[k][tx * 4];
            float4 wv = *(const float4*)&Wv[k][tx * 4];
            #pragma unroll
            for (int r = 0; r < 2; r++) {
                float a = xs[ty * 2 + r][k0 + k];
                aU[r][0] += a * wu.x; aU[r][1] += a * wu.y;
                aU[r][2] += a * wu.z; aU[r][3] += a * wu.w;
                aV[r][0] += a * wv.x; aV[r][1] += a * wv.y;
                aV[r][2] += a * wv.z; aV[r][3] += a * wv.w;
            }
        }
        __syncthreads();
    }

    #pragma unroll
    for (int r = 0; r < 2; r++) {
        size_t row = (size_t)(base + ty * 2 + r) * 64 + tx * 4;
        *(float4*)(U + row) = make_float4(aU[r][0], aU[r][1], aU[r][2], aU[r][3]);
        *(float4*)(V + row) = make_float4(aV[r][0], aV[r][1], aV[r][2], aV[r][3]);
    }
}

// ---------------- edge scorer ----------------
__global__ void edge_scores(const float* __restrict__ U, const float* __restrict__ V,
                            const float* __restrict__ eb1, const float* __restrict__ eW2,
                            const float* __restrict__ eb2, float* __restrict__ S)
{
    int b = blockIdx.z;
    int i0 = blockIdx.y * 32, j0 = blockIdx.x * 32;
    __shared__ float Ush[32][65], Vsh[32][65];
    __shared__ float w2[64], b1[64];
    int tid = threadIdx.x;
    if (tid < 64) { w2[tid] = eW2[tid]; b1[tid] = eb1[tid]; }
    for (int idx = tid; idx < 32 * 64; idx += 256) {
        int r = idx >> 6, h = idx & 63;
        Ush[r][h] = U[((size_t)b * Nn + i0 + r) * 64 + h];
        Vsh[r][h] = V[((size_t)b * Nn + j0 + r) * 64 + h];
    }
    __syncthreads();
    int tx = tid & 31;
    int ty = tid >> 5;
    float acc[4] = {0, 0, 0, 0};
    for (int h = 0; h < 64; h++) {
        float vj = Vsh[tx][h];
        float wb = w2[h], bb = b1[h];
        #pragma unroll
        for (int r = 0; r < 4; r++) {
            float t = Ush[ty * 4 + r][h] + vj + bb;
            acc[r] += fmaxf(t, 0.0f) * wb;
        }
    }
    float e2 = eb2[0];
    #pragma unroll
    for (int r = 0; r < 4; r++)
        S[((size_t)b * Nn + i0 + ty * 4 + r) * Nn + j0 + tx] = acc[r] + e2;
}

// AP = masked strict-upper exp(0.5*(S+S^T)); RS = row sums (0 -> 1)
__global__ void ap_rowsum(const float* __restrict__ S, const float* __restrict__ mask,
                          float* __restrict__ AP, float* __restrict__ RS)
{
    int bi = blockIdx.x;
    int b = bi >> 7, i = bi & 127;
    int j = threadIdx.x;
    float v = 0.0f;
    if (j > i) {
        float mm = mask[b * Nn + i] * mask[b * Nn + j];
        if (mm != 0.0f)
            v = expf(0.5f * (S[(size_t)bi * Nn + j] + S[((size_t)b * Nn + j) * Nn + i]));
    }
    AP[(size_t)bi * Nn + j] = v;
    __shared__ float red[128];
    red[j] = v;
    __syncthreads();
    for (int s = 64; s > 0; s >>= 1) {
        if (j < s) red[j] += red[j + s];
        __syncthreads();
    }
    if (j == 0) { float rs = red[0]; RS[bi] = (rs == 0.0f) ? 1.0f : rs; }
}

__global__ void build_An(const float* __restrict__ AP, const float* __restrict__ RS,
                         float* __restrict__ An)
{
    int bi = blockIdx.x;
    int b = bi >> 7, i = bi & 127;
    int j = threadIdx.x;
    An[(size_t)bi * Nn + j] = AP[(size_t)bi * Nn + j] / RS[bi]
                            + AP[((size_t)b * Nn + j) * Nn + i] / RS[b * Nn + j];
}

// Fused degree + normalized Laplacian
__global__ void degree_build_L(const float* __restrict__ M, float* __restrict__ L)
{
    int b = blockIdx.x;
    int j = threadIdx.x;
    const float* Mb = M + (size_t)b * Nn * Nn;
    float* Lb = L + (size_t)b * Nn * Nn;
    __shared__ float Dsh[Nn];
    float s = 0.0f;
    for (int i = 0; i < Nn; i++) s += Mb[(size_t)i * Nn + j];
    float dj = 1.0f / sqrtf(s + 1e-5f);
    Dsh[j] = dj;
    __syncthreads();
    for (int i = 0; i < Nn; i++)
        Lb[(size_t)i * Nn + j] = Dsh[i] * Mb[(size_t)i * Nn + j] * dj;
}

// write X into Z columns [0,fin) and [3fin,4fin)
__global__ void copy_xz(const float* __restrict__ X, float* __restrict__ Z,
                        int fin, int ldz)
{
    int r = blockIdx.x;
    for (int c = threadIdx.x; c < fin; c += blockDim.x) {
        float v = X[(size_t)r * fin + c];
        Z[(size_t)r * ldz + c] = v;
        Z[(size_t)r * ldz + 3 * fin + c] = v;
    }
}

// Fused maxpool + classifier head
__global__ void pool_classifier(const float* __restrict__ H,
                                const float* __restrict__ fW1, const float* __restrict__ fb1,
                                const float* __restrict__ fW2, const float* __restrict__ fb2,
                                float* __restrict__ out)
{
    int b = blockIdx.x;
    int tid = threadIdx.x;  // 512 threads
    __shared__ float sp[512];
    __shared__ float st[256];
    {
        float m = -3.4e38f;
        const float* Hb = H + (size_t)b * Nn * 512 + tid;
        for (int n = 0; n < Nn; n++)
            m = fmaxf(m, Hb[(size_t)n * 512]);
        sp[tid] = m;
    }
    __syncthreads();
    if (tid < 256) {
        float t = fb1[tid];
        for (int k = 0; k < 512; k++) t += sp[k] * fW1[k * 256 + tid];
        st[tid] = t;
    }
    __syncthreads();
    if (tid < 10) {
        float o = fb2[tid];
        for (int h = 0; h < 256; h++) o += st[h] * fW2[h * 10 + tid];
        out[b * 10 + tid] = o;
    }
}

// ---------------- driver ----------------
extern "C" void kernel_launch(void* const* d_in, const int* in_sizes, int n_in,
                              void* d_out, int out_size)
{
    const float* x    = (const float*)d_in[0];
    const float* A    = (const float*)d_in[1];
    const float* mask = (const float*)d_in[2];
    const float* eW1  = (const float*)d_in[3];
    const float* eb1  = (const float*)d_in[4];
    const float* eW2  = (const float*)d_in[5];
    const float* eb2  = (const float*)d_in[6];
    const float* gW[3], *gb[3], *gg[3], *gbe[3], *gm[3], *gv[3];
    for (int li = 0; li < 3; li++) {
        int base = 7 + li * 6;
        gW[li]  = (const float*)d_in[base + 0];
        gb[li]  = (const float*)d_in[base + 1];
        gg[li]  = (const float*)d_in[base + 2];
        gbe[li] = (const float*)d_in[base + 3];
        gm[li]  = (const float*)d_in[base + 4];
        gv[li]  = (const float*)d_in[base + 5];
    }
    const float* fW1 = (const float*)d_in[25];
    const float* fb1 = (const float*)d_in[26];
    const float* fW2 = (const float*)d_in[27];
    const float* fb2 = (const float*)d_in[28];

    float* buf = nullptr;
    cudaGetSymbolAddress((void**)&buf, g_buf);
    float* U  = buf + OFF_U;
    float* V  = buf + OFF_V;
    float* S  = buf + OFF_S;
    float* AP = buf + OFF_AP;
    float* RS = buf + OFF_RS;
    float* An = buf + OFF_AN;
    float* L0 = buf + OFF_L0;
    float* L1 = buf + OFF_L1;
    float* M0 = buf + OFF_M0;
    float* M1 = buf + OFF_M1;
    float* Z  = buf + OFF_Z;
    float* Hb[3] = { buf + OFF_H0, buf + OFF_H1, buf + OFF_H2 };

    // edge adjacency path
    uv_proj<<<128, 256>>>(x, eW1, U, V);
    edge_scores<<<dim3(4, 4, Bsz), 256>>>(U, V, eb1, eW2, eb2, S);
    ap_rowsum<<<Bsz * Nn, 128>>>(S, mask, AP, RS);
    build_An<<<Bsz * Nn, 128>>>(AP, RS, An);
    degree_build_L<<<Bsz, 128>>>(A, L0);
    degree_build_L<<<Bsz, 128>>>(An, L1);
    build_M<<<dim3(2, 1, 2 * Bsz), 256>>>(L0, L1, M0, M1);

    // 3 graph-conv layers
    const float* Xin = x;
    int fin = 128;
    int fouts[3] = { 64, 256, 512 };
    for (int li = 0; li < 3; li++) {
        int ldz = 6 * fin;
        copy_xz<<<Bsz * Nn, 128>>>(Xin, Z, fin, ldz);
        cheb_tc<<<dim3(fin / 64, 1, 4 * Bsz), 256>>>(L0, M0, L1, M1, Xin, fin, Z, ldz, fin);
        int fo = fouts[li];
        gemm_tc<<<dim3(fo / 64, 32), 256>>>(Z, ldz, gW[li], fo, Hb[li], fo, 6 * fin,
                                            gb[li], mask, gg[li], gbe[li], gm[li], gv[li]);
        Xin = Hb[li];
        fin = fo;
    }

    pool_classifier<<<Bsz, 512>>>(Hb[2], fW1, fb1, fW2, fb2, (float*)d_out);
}